// round 15
// baseline (speedup 1.0000x reference)
#include <cuda_runtime.h>
#include <cuda_fp16.h>

#define N_NODES 100000
#define IN_DIM  1024
#define OUT_DIM 256
#define NNZ_X   3200000
#define NNZ_ADJ 3200000

#define SCAN_B    1024
#define N_SCANBLK ((N_NODES + SCAN_B - 1) / SCAN_B)   // 98

// ---------------- scratch (__device__ globals; no allocs allowed) ----------
__device__ __half g_xw[(size_t)N_NODES * OUT_DIM];     // 51.2 MB (L2-resident)
__device__ __half g_wh[IN_DIM * OUT_DIM];              // 512 KB

// Counters rely on zero-init at module load + self-restoring property:
// hist adds each node's count, scatter atomicSub's it back to exactly 0.
__device__ int   g_counts_x[N_NODES];
__device__ int   g_counts_a[N_NODES];
__device__ int   g_offs_x[N_NODES + 1];
__device__ int   g_offs_a[N_NODES + 1];
// decoupled-lookback status (epoch-tagged; NEVER needs reset across replays)
__device__ int   g_agg_x[N_SCANBLK];
__device__ int   g_agg_a[N_SCANBLK];
__device__ int   g_tick_x;
__device__ int   g_tick_a;
__device__ int   g_cx[NNZ_X];                          // packed (col<<16)|fp16
__device__ int   g_ca[NNZ_ADJ];                        // packed (col<<15)|q15

// ---------------- mixed-precision FMA: fp16 x fp16 -> fp32 accum ------------
__device__ __forceinline__ void fma_h2(float& s0, float& s1, int wpair, unsigned short vh) {
    unsigned short h0, h1;
    asm("mov.b32 {%0, %1}, %2;" : "=h"(h0), "=h"(h1) : "r"(wpair));
    asm("fma.rn.f32.f16 %0, %1, %2, %0;" : "+f"(s0) : "h"(h0), "h"(vh));
    asm("fma.rn.f32.f16 %0, %1, %2, %0;" : "+f"(s1) : "h"(h1), "h"(vh));
}

// ---------------- W fp32 -> fp16 -------------------------------------------
__global__ void wcvt_kernel(const float* __restrict__ W, __half* __restrict__ Wh) {
    int i = blockIdx.x * blockDim.x + threadIdx.x;      // over float2 pairs
    if (i < IN_DIM * OUT_DIM / 2) {
        float2 w = __ldcs(reinterpret_cast<const float2*>(W) + i);
        reinterpret_cast<__half2*>(Wh)[i] = __floats2half2_rn(w.x, w.y);
    }
}

// ---------------- histogram: int4-vectorized, 4 nnz per thread --------------
__global__ void hist_kernel(const int4* __restrict__ rows4, int* __restrict__ counts, int n4) {
    int i = blockIdx.x * blockDim.x + threadIdx.x;
    if (i < n4) {
        int4 r = __ldcs(&rows4[i]);
        atomicAdd(&counts[r.x], 1);
        atomicAdd(&counts[r.y], 1);
        atomicAdd(&counts[r.z], 1);
        atomicAdd(&counts[r.w], 1);
    }
}

// ---------------- single-pass scan: block scan + decoupled lookback ----------
// agg[b] word layout: bits[24:31) = epoch tag (1..127, never 0), bits[0:24) = block total.
// Epoch from a monotonic ticket counter -> stale words from earlier graph
// replays never match the current tag, so no reset pass is needed.
// All 98 blocks are co-resident (<=296 slots for 1024-thr blocks) -> spin is safe.
__global__ void scan_kernel(const int* __restrict__ counts, int* __restrict__ offs,
                            int* __restrict__ agg, int* __restrict__ ticket, int total) {
    __shared__ int wsum[32];
    __shared__ int sh_tag;
    __shared__ int sh_boff;
    int t = threadIdx.x, lane = t & 31, wid = t >> 5;
    int b = blockIdx.x;

    if (t == 0) {
        int tk = atomicAdd(ticket, 1);
        sh_tag = (((tk / N_SCANBLK) % 127) + 1) << 24;
    }

    // block-local inclusive scan (two-level warp shuffle)
    int i = b * SCAN_B + t;
    int v = (i < N_NODES) ? counts[i] : 0;
    int s = v;
#pragma unroll
    for (int d = 1; d < 32; d <<= 1) {
        int u = __shfl_up_sync(0xffffffffu, s, d);
        if (lane >= d) s += u;
    }
    if (lane == 31) wsum[wid] = s;
    __syncthreads();                                    // also publishes sh_tag
    int tag = sh_tag;
    if (wid == 0) {
        int ws = wsum[lane];
#pragma unroll
        for (int d = 1; d < 32; d <<= 1) {
            int u = __shfl_up_sync(0xffffffffu, ws, d);
            if (lane >= d) ws += u;
        }
        wsum[lane] = ws;
    }
    __syncthreads();
    int incl = s + (wid ? wsum[wid - 1] : 0);

    // publish this block's total (last thread holds it)
    if (t == SCAN_B - 1) atomicExch(&agg[b], tag | incl);

    // warp 0: parallel lookback over predecessors
    if (wid == 0) {
        int sum = 0;
        for (int j0 = 0; j0 < b; j0 += 32) {
            int j = j0 + lane;
            int val = 0;
            if (j < b) {
                int w;
                do { w = atomicAdd(&agg[j], 0); } while ((w & 0x7f000000) != tag);
                val = w & 0x00ffffff;
            }
#pragma unroll
            for (int d = 16; d > 0; d >>= 1) val += __shfl_down_sync(0xffffffffu, val, d);
            if (lane == 0) sum += val;
        }
        if (lane == 0) sh_boff = sum;
    }
    __syncthreads();
    int boff = sh_boff;

    if (i < N_NODES) offs[i] = boff + incl - v;         // exclusive prefix
    if (i == 0) offs[N_NODES] = total;
}

// ---------------- scatter COO -> CSR: float4/int4-vectorized, packed payload -
// MODE 0 (x):   col < 1024   -> p = (col<<16) | fp16(val) bits
// MODE 1 (adj): col < 2^17, val in [0,1) -> p = (col<<15) | round(val*32768) clamped
template <int MODE>
__global__ void scatter_kernel(const int4* __restrict__ rows4, const int4* __restrict__ cols4,
                               const float4* __restrict__ vals4,
                               const int* __restrict__ offs, int* __restrict__ cnt,
                               int* __restrict__ cdata, int n4) {
    int i = blockIdx.x * blockDim.x + threadIdx.x;
    if (i >= n4) return;
    int4   r = __ldcs(&rows4[i]);
    int4   c = __ldcs(&cols4[i]);
    float4 v = __ldcs(&vals4[i]);
#define SCAT_ONE(RR, CC, VV)                                                     \
    {                                                                            \
        int p = offs[(RR)] + atomicSub(&cnt[(RR)], 1) - 1;                       \
        int packed;                                                              \
        if (MODE == 0) {                                                         \
            packed = ((CC) << 16) | (int)__half_as_ushort(__float2half_rn(VV));  \
        } else {                                                                 \
            int q = __float2int_rn((VV) * 32768.f);                              \
            q = min(q, 32767);                                                   \
            packed = ((CC) << 15) | q;                                           \
        }                                                                        \
        cdata[p] = packed;                                                       \
    }
    SCAT_ONE(r.x, c.x, v.x)
    SCAT_ONE(r.y, c.y, v.y)
    SCAT_ONE(r.z, c.z, v.z)
    SCAT_ONE(r.w, c.w, v.w)
#undef SCAT_ONE
}

// ---------------- SpMM1 step: uniform scalar payload load (no shfl) ---------
#define SPMM1_STEP(IDX)                                                          \
    {                                                                            \
        int p = __ldg(&cdata[(IDX)]);   /* all lanes same addr -> broadcast */   \
        int cc = ((unsigned)p) >> 16;                                            \
        unsigned short vh = (unsigned short)(p & 0xffff);                        \
        int4 wv = __ldg(reinterpret_cast<const int4*>(Wh + (size_t)cc * OUT_DIM) + lane); \
        fma_h2(a0, a1, wv.x, vh);                                                \
        fma_h2(a2, a3, wv.y, vh);                                                \
        fma_h2(a4, a5, wv.z, vh);                                                \
        fma_h2(a6, a7, wv.w, vh);                                                \
    }

// ---------------- SpMM1: warp per row (frozen) --------------------------------
__global__ void __launch_bounds__(256, 8)
spmm1_kernel(const int* __restrict__ offs, const int* __restrict__ cdata,
             const __half* __restrict__ Wh, __half* __restrict__ xw) {
    int warp = (blockIdx.x * blockDim.x + threadIdx.x) >> 5;
    int lane = threadIdx.x & 31;
    if (warp >= N_NODES) return;

    int beg = offs[warp];
    int end = offs[warp + 1];

    float a0 = 0.f, a1 = 0.f, a2 = 0.f, a3 = 0.f;
    float a4 = 0.f, a5 = 0.f, a6 = 0.f, a7 = 0.f;

    int base = beg;
    for (; base + 32 <= end; base += 32) {
#pragma unroll
        for (int t = 0; t < 32; t++) SPMM1_STEP(base + t)
    }
    for (; base < end; base++) SPMM1_STEP(base)

    int4 o;
    __half2 h0 = __floats2half2_rn(a0, a1);
    __half2 h1 = __floats2half2_rn(a2, a3);
    __half2 h2 = __floats2half2_rn(a4, a5);
    __half2 h3 = __floats2half2_rn(a6, a7);
    o.x = *reinterpret_cast<int*>(&h0);
    o.y = *reinterpret_cast<int*>(&h1);
    o.z = *reinterpret_cast<int*>(&h2);
    o.w = *reinterpret_cast<int*>(&h3);
    reinterpret_cast<int4*>(xw + (size_t)warp * OUT_DIM)[lane] = o;
}

// ---------------- SpMM2 step: uniform scalar payload load (no shfl) ---------
#define SPMM2_STEP(IDX)                                                          \
    {                                                                            \
        int p = __ldg(&cdata[(IDX)]);                                            \
        int cc = ((unsigned)p) >> 15;                                            \
        float vv = (float)(p & 0x7fff) * QINV;                                   \
        int4 wv = __ldg(reinterpret_cast<const int4*>(xw + (size_t)cc * OUT_DIM) + lane); \
        float2 f0 = __half22float2(*reinterpret_cast<__half2*>(&wv.x));          \
        float2 f1 = __half22float2(*reinterpret_cast<__half2*>(&wv.y));          \
        float2 f2 = __half22float2(*reinterpret_cast<__half2*>(&wv.z));          \
        float2 f3 = __half22float2(*reinterpret_cast<__half2*>(&wv.w));          \
        a0 = fmaf(vv, f0.x, a0); a1 = fmaf(vv, f0.y, a1);                        \
        a2 = fmaf(vv, f1.x, a2); a3 = fmaf(vv, f1.y, a3);                        \
        a4 = fmaf(vv, f2.x, a4); a5 = fmaf(vv, f2.y, a5);                        \
        a6 = fmaf(vv, f3.x, a6); a7 = fmaf(vv, f3.y, a7);                        \
    }

// ---------------- SpMM2 + ReLU (frozen) ---------------------------------------
__global__ void __launch_bounds__(256, 8)
spmm2_kernel(const int* __restrict__ offs, const int* __restrict__ cdata,
             const __half* __restrict__ xw, float* __restrict__ out) {
    int warp = (blockIdx.x * blockDim.x + threadIdx.x) >> 5;
    int lane = threadIdx.x & 31;
    if (warp >= N_NODES) return;

    int beg = offs[warp];
    int end = offs[warp + 1];

    float a0 = 0.f, a1 = 0.f, a2 = 0.f, a3 = 0.f;
    float a4 = 0.f, a5 = 0.f, a6 = 0.f, a7 = 0.f;

    const float QINV = 1.f / 32768.f;

    int base = beg;
    for (; base + 32 <= end; base += 32) {
#pragma unroll
        for (int t = 0; t < 32; t++) SPMM2_STEP(base + t)
    }
    for (; base < end; base++) SPMM2_STEP(base)

    float4* d = reinterpret_cast<float4*>(out + (size_t)warp * OUT_DIM) + lane * 2;
    __stcs(d,     make_float4(fmaxf(a0, 0.f), fmaxf(a1, 0.f), fmaxf(a2, 0.f), fmaxf(a3, 0.f)));
    __stcs(d + 1, make_float4(fmaxf(a4, 0.f), fmaxf(a5, 0.f), fmaxf(a6, 0.f), fmaxf(a7, 0.f)));
}

// ---------------------------------------------------------------------------
extern "C" void kernel_launch(void* const* d_in, const int* in_sizes, int n_in,
                              void* d_out, int out_size) {
    const int*   x_rows   = (const int*)  d_in[0];
    const int*   x_cols   = (const int*)  d_in[1];
    const float* x_vals   = (const float*)d_in[2];
    const int*   adj_rows = (const int*)  d_in[3];
    const int*   adj_cols = (const int*)  d_in[4];
    const float* adj_vals = (const float*)d_in[5];
    const float* W        = (const float*)d_in[6];
    float*       out      = (float*)d_out;

    __half *xw, *Wh;
    int *cntx, *cnta, *ox, *oa, *aggx, *agga, *tkx, *tka, *cx, *ca;
    cudaGetSymbolAddress((void**)&xw,   g_xw);
    cudaGetSymbolAddress((void**)&Wh,   g_wh);
    cudaGetSymbolAddress((void**)&cntx, g_counts_x);
    cudaGetSymbolAddress((void**)&cnta, g_counts_a);
    cudaGetSymbolAddress((void**)&ox,   g_offs_x);
    cudaGetSymbolAddress((void**)&oa,   g_offs_a);
    cudaGetSymbolAddress((void**)&aggx, g_agg_x);
    cudaGetSymbolAddress((void**)&agga, g_agg_a);
    cudaGetSymbolAddress((void**)&tkx,  g_tick_x);
    cudaGetSymbolAddress((void**)&tka,  g_tick_a);
    cudaGetSymbolAddress((void**)&cx,   g_cx);
    cudaGetSymbolAddress((void**)&ca,   g_ca);

    // Side stream + events: created once on first (uncaptured) call, reused.
    static cudaStream_t s2 = nullptr;
    static cudaEvent_t  evFork = nullptr, evJoin = nullptr, evW = nullptr;
    if (s2 == nullptr) {
        cudaStreamCreateWithFlags(&s2, cudaStreamNonBlocking);
        cudaEventCreateWithFlags(&evFork, cudaEventDisableTiming);
        cudaEventCreateWithFlags(&evJoin, cudaEventDisableTiming);
        cudaEventCreateWithFlags(&evW,    cudaEventDisableTiming);
    }

    const int n4        = NNZ_X / 4;                       // 800000
    const int n4_blocks = (n4 + 255) / 256;

    // ---- fork (counters are self-zeroed; no zero pass needed) ----
    cudaEventRecord(evFork, 0);
    cudaStreamWaitEvent(s2, evFork, 0);

    // ---- chain B (W convert + adj build) on side stream ----
    wcvt_kernel<<<(IN_DIM * OUT_DIM / 2 + 255) / 256, 256, 0, s2>>>(W, Wh);
    cudaEventRecord(evW, s2);                       // spmm1 depends on Wh
    hist_kernel<<<n4_blocks, 256, 0, s2>>>((const int4*)adj_rows, cnta, n4);
    scan_kernel<<<N_SCANBLK, SCAN_B, 0, s2>>>(cnta, oa, agga, tka, NNZ_ADJ);
    scatter_kernel<1><<<n4_blocks, 256, 0, s2>>>((const int4*)adj_rows, (const int4*)adj_cols,
                                                 (const float4*)adj_vals, oa, cnta, ca, n4);
    cudaEventRecord(evJoin, s2);

    // ---- chain A (x build + spmm1) on main stream ----
    hist_kernel<<<n4_blocks, 256>>>((const int4*)x_rows, cntx, n4);
    scan_kernel<<<N_SCANBLK, SCAN_B>>>(cntx, ox, aggx, tkx, NNZ_X);
    scatter_kernel<0><<<n4_blocks, 256>>>((const int4*)x_rows, (const int4*)x_cols,
                                          (const float4*)x_vals, ox, cntx, cx, n4);

    cudaStreamWaitEvent(0, evW, 0);                 // ensure Wh ready
    const int spmm_blocks = (N_NODES * 32 + 255) / 256;   // warp per row
    spmm1_kernel<<<spmm_blocks, 256>>>(ox, cx, Wh, xw);

    // ---- join, then SpMM2 + ReLU ----
    cudaStreamWaitEvent(0, evJoin, 0);
    spmm2_kernel<<<spmm_blocks, 256>>>(oa, ca, xw, out);
}

// round 16
// speedup vs baseline: 1.0095x; 1.0095x over previous
#include <cuda_runtime.h>
#include <cuda_fp16.h>

#define N_NODES 100000
#define IN_DIM  1024
#define OUT_DIM 256
#define NNZ_X   3200000
#define NNZ_ADJ 3200000

#define SCAN_B    1024
#define N_SCANBLK ((N_NODES + SCAN_B - 1) / SCAN_B)   // 98

// ---------------- scratch (__device__ globals; no allocs allowed) ----------
__device__ __half g_xw[(size_t)N_NODES * OUT_DIM];     // 51.2 MB (L2-resident)
__device__ __half g_wh[IN_DIM * OUT_DIM];              // 512 KB

// counts: zero at module load; scanC re-zeroes each replay (self-restoring).
// cur:    rewritten by scanC from offs each replay before scatter uses it.
__device__ int   g_counts_x[N_NODES];
__device__ int   g_counts_a[N_NODES];
__device__ int   g_cur_x[N_NODES];
__device__ int   g_cur_a[N_NODES];
__device__ int   g_offs_x[N_NODES + 1];
__device__ int   g_offs_a[N_NODES + 1];
__device__ int   g_bsums_x[N_SCANBLK];
__device__ int   g_bsums_a[N_SCANBLK];
__device__ int   g_cx[NNZ_X];                          // packed (col<<16)|fp16
__device__ int   g_ca[NNZ_ADJ];                        // packed (col<<15)|q15

// ---------------- mixed-precision FMA: fp16 x fp16 -> fp32 accum ------------
__device__ __forceinline__ void fma_h2(float& s0, float& s1, int wpair, unsigned short vh) {
    unsigned short h0, h1;
    asm("mov.b32 {%0, %1}, %2;" : "=h"(h0), "=h"(h1) : "r"(wpair));
    asm("fma.rn.f32.f16 %0, %1, %2, %0;" : "+f"(s0) : "h"(h0), "h"(vh));
    asm("fma.rn.f32.f16 %0, %1, %2, %0;" : "+f"(s1) : "h"(h1), "h"(vh));
}

// ---------------- W fp32 -> fp16 -------------------------------------------
__global__ void wcvt_kernel(const float* __restrict__ W, __half* __restrict__ Wh) {
    int i = blockIdx.x * blockDim.x + threadIdx.x;      // over float2 pairs
    if (i < IN_DIM * OUT_DIM / 2) {
        float2 w = __ldcs(reinterpret_cast<const float2*>(W) + i);
        reinterpret_cast<__half2*>(Wh)[i] = __floats2half2_rn(w.x, w.y);
    }
}

// ---------------- histogram: int4-vectorized, 4 nnz per thread --------------
__global__ void hist_kernel(const int4* __restrict__ rows4, int* __restrict__ counts, int n4) {
    int i = blockIdx.x * blockDim.x + threadIdx.x;
    if (i < n4) {
        int4 r = __ldcs(&rows4[i]);
        atomicAdd(&counts[r.x], 1);
        atomicAdd(&counts[r.y], 1);
        atomicAdd(&counts[r.z], 1);
        atomicAdd(&counts[r.w], 1);
    }
}

// ---------------- scan A: two-level warp-shuffle exclusive scan --------------
__global__ void scanA_kernel(const int* __restrict__ counts,
                             int* __restrict__ offs, int* __restrict__ bsums) {
    __shared__ int wsum[32];
    int t = threadIdx.x, lane = t & 31, wid = t >> 5;
    int i = blockIdx.x * SCAN_B + t;
    int v = (i < N_NODES) ? counts[i] : 0;
    int s = v;
#pragma unroll
    for (int d = 1; d < 32; d <<= 1) {
        int u = __shfl_up_sync(0xffffffffu, s, d);
        if (lane >= d) s += u;
    }
    if (lane == 31) wsum[wid] = s;
    __syncthreads();
    if (wid == 0) {
        int ws = wsum[lane];
#pragma unroll
        for (int d = 1; d < 32; d <<= 1) {
            int u = __shfl_up_sync(0xffffffffu, ws, d);
            if (lane >= d) ws += u;
        }
        wsum[lane] = ws;
    }
    __syncthreads();
    int incl = s + (wid ? wsum[wid - 1] : 0);
    if (i < N_NODES) offs[i] = incl - v;                // exclusive (local)
    if (t == SCAN_B - 1) bsums[blockIdx.x] = incl;      // inclusive block total
}

// ---------------- scan C: add prefix; init cursor; reset counts -------------
__global__ void scanC_kernel(int* __restrict__ offs, const int* __restrict__ bsums,
                             int* __restrict__ cur, int* __restrict__ counts, int total) {
    __shared__ int part[4];
    __shared__ int pref;
    int t = threadIdx.x, lane = t & 31, wid = t >> 5;
    if (t < 128) {
        int v = (t < blockIdx.x) ? bsums[t] : 0;        // blockIdx.x <= 97 < 128
#pragma unroll
        for (int d = 16; d > 0; d >>= 1) v += __shfl_down_sync(0xffffffffu, v, d);
        if (lane == 0) part[wid] = v;
    }
    __syncthreads();
    if (t == 0) pref = part[0] + part[1] + part[2] + part[3];
    __syncthreads();
    int i = blockIdx.x * SCAN_B + t;
    if (i < N_NODES) {
        int o = offs[i] + pref;
        offs[i]   = o;
        cur[i]    = o;                                  // scatter cursor
        counts[i] = 0;                                  // restore for next replay
    }
    if (i == 0) offs[N_NODES] = total;
}

// ---------------- scatter COO -> CSR: ONE atomic + ONE store per nnz ---------
// MODE 0 (x):   col < 1024   -> p = (col<<16) | fp16(val) bits
// MODE 1 (adj): col < 2^17, val in [0,1) -> p = (col<<15) | round(val*32768) clamped
template <int MODE>
__global__ void scatter_kernel(const int4* __restrict__ rows4, const int4* __restrict__ cols4,
                               const float4* __restrict__ vals4,
                               int* __restrict__ cur, int* __restrict__ cdata, int n4) {
    int i = blockIdx.x * blockDim.x + threadIdx.x;
    if (i >= n4) return;
    int4   r = __ldcs(&rows4[i]);
    int4   c = __ldcs(&cols4[i]);
    float4 v = __ldcs(&vals4[i]);
#define SCAT_ONE(RR, CC, VV)                                                     \
    {                                                                            \
        int p = atomicAdd(&cur[(RR)], 1);                                        \
        int packed;                                                              \
        if (MODE == 0) {                                                         \
            packed = ((CC) << 16) | (int)__half_as_ushort(__float2half_rn(VV));  \
        } else {                                                                 \
            int q = __float2int_rn((VV) * 32768.f);                              \
            q = min(q, 32767);                                                   \
            packed = ((CC) << 15) | q;                                           \
        }                                                                        \
        cdata[p] = packed;                                                       \
    }
    SCAT_ONE(r.x, c.x, v.x)
    SCAT_ONE(r.y, c.y, v.y)
    SCAT_ONE(r.z, c.z, v.z)
    SCAT_ONE(r.w, c.w, v.w)
#undef SCAT_ONE
}

// ---------------- SpMM1 step: uniform scalar payload load (no shfl) ---------
#define SPMM1_STEP(IDX)                                                          \
    {                                                                            \
        int p = __ldg(&cdata[(IDX)]);   /* all lanes same addr -> broadcast */   \
        int cc = ((unsigned)p) >> 16;                                            \
        unsigned short vh = (unsigned short)(p & 0xffff);                        \
        int4 wv = __ldg(reinterpret_cast<const int4*>(Wh + (size_t)cc * OUT_DIM) + lane); \
        fma_h2(a0, a1, wv.x, vh);                                                \
        fma_h2(a2, a3, wv.y, vh);                                                \
        fma_h2(a4, a5, wv.z, vh);                                                \
        fma_h2(a6, a7, wv.w, vh);                                                \
    }

// ---------------- SpMM1: warp per row (frozen) --------------------------------
__global__ void __launch_bounds__(256, 8)
spmm1_kernel(const int* __restrict__ offs, const int* __restrict__ cdata,
             const __half* __restrict__ Wh, __half* __restrict__ xw) {
    int warp = (blockIdx.x * blockDim.x + threadIdx.x) >> 5;
    int lane = threadIdx.x & 31;
    if (warp >= N_NODES) return;

    int beg = offs[warp];
    int end = offs[warp + 1];

    float a0 = 0.f, a1 = 0.f, a2 = 0.f, a3 = 0.f;
    float a4 = 0.f, a5 = 0.f, a6 = 0.f, a7 = 0.f;

    int base = beg;
    for (; base + 32 <= end; base += 32) {
#pragma unroll
        for (int t = 0; t < 32; t++) SPMM1_STEP(base + t)
    }
    for (; base < end; base++) SPMM1_STEP(base)

    int4 o;
    __half2 h0 = __floats2half2_rn(a0, a1);
    __half2 h1 = __floats2half2_rn(a2, a3);
    __half2 h2 = __floats2half2_rn(a4, a5);
    __half2 h3 = __floats2half2_rn(a6, a7);
    o.x = *reinterpret_cast<int*>(&h0);
    o.y = *reinterpret_cast<int*>(&h1);
    o.z = *reinterpret_cast<int*>(&h2);
    o.w = *reinterpret_cast<int*>(&h3);
    reinterpret_cast<int4*>(xw + (size_t)warp * OUT_DIM)[lane] = o;
}

// ---------------- SpMM2 step: uniform scalar payload load (no shfl) ---------
#define SPMM2_STEP(IDX)                                                          \
    {                                                                            \
        int p = __ldg(&cdata[(IDX)]);                                            \
        int cc = ((unsigned)p) >> 15;                                            \
        float vv = (float)(p & 0x7fff) * QINV;                                   \
        int4 wv = __ldg(reinterpret_cast<const int4*>(xw + (size_t)cc * OUT_DIM) + lane); \
        float2 f0 = __half22float2(*reinterpret_cast<__half2*>(&wv.x));          \
        float2 f1 = __half22float2(*reinterpret_cast<__half2*>(&wv.y));          \
        float2 f2 = __half22float2(*reinterpret_cast<__half2*>(&wv.z));          \
        float2 f3 = __half22float2(*reinterpret_cast<__half2*>(&wv.w));          \
        a0 = fmaf(vv, f0.x, a0); a1 = fmaf(vv, f0.y, a1);                        \
        a2 = fmaf(vv, f1.x, a2); a3 = fmaf(vv, f1.y, a3);                        \
        a4 = fmaf(vv, f2.x, a4); a5 = fmaf(vv, f2.y, a5);                        \
        a6 = fmaf(vv, f3.x, a6); a7 = fmaf(vv, f3.y, a7);                        \
    }

// ---------------- SpMM2 + ReLU (frozen) ---------------------------------------
__global__ void __launch_bounds__(256, 8)
spmm2_kernel(const int* __restrict__ offs, const int* __restrict__ cdata,
             const __half* __restrict__ xw, float* __restrict__ out) {
    int warp = (blockIdx.x * blockDim.x + threadIdx.x) >> 5;
    int lane = threadIdx.x & 31;
    if (warp >= N_NODES) return;

    int beg = offs[warp];
    int end = offs[warp + 1];

    float a0 = 0.f, a1 = 0.f, a2 = 0.f, a3 = 0.f;
    float a4 = 0.f, a5 = 0.f, a6 = 0.f, a7 = 0.f;

    const float QINV = 1.f / 32768.f;

    int base = beg;
    for (; base + 32 <= end; base += 32) {
#pragma unroll
        for (int t = 0; t < 32; t++) SPMM2_STEP(base + t)
    }
    for (; base < end; base++) SPMM2_STEP(base)

    float4* d = reinterpret_cast<float4*>(out + (size_t)warp * OUT_DIM) + lane * 2;
    __stcs(d,     make_float4(fmaxf(a0, 0.f), fmaxf(a1, 0.f), fmaxf(a2, 0.f), fmaxf(a3, 0.f)));
    __stcs(d + 1, make_float4(fmaxf(a4, 0.f), fmaxf(a5, 0.f), fmaxf(a6, 0.f), fmaxf(a7, 0.f)));
}

// ---------------------------------------------------------------------------
extern "C" void kernel_launch(void* const* d_in, const int* in_sizes, int n_in,
                              void* d_out, int out_size) {
    const int*   x_rows   = (const int*)  d_in[0];
    const int*   x_cols   = (const int*)  d_in[1];
    const float* x_vals   = (const float*)d_in[2];
    const int*   adj_rows = (const int*)  d_in[3];
    const int*   adj_cols = (const int*)  d_in[4];
    const float* adj_vals = (const float*)d_in[5];
    const float* W        = (const float*)d_in[6];
    float*       out      = (float*)d_out;

    __half *xw, *Wh;
    int *cntx, *cnta, *curx, *cura, *ox, *oa, *bx, *ba, *cx, *ca;
    cudaGetSymbolAddress((void**)&xw,   g_xw);
    cudaGetSymbolAddress((void**)&Wh,   g_wh);
    cudaGetSymbolAddress((void**)&cntx, g_counts_x);
    cudaGetSymbolAddress((void**)&cnta, g_counts_a);
    cudaGetSymbolAddress((void**)&curx, g_cur_x);
    cudaGetSymbolAddress((void**)&cura, g_cur_a);
    cudaGetSymbolAddress((void**)&ox,   g_offs_x);
    cudaGetSymbolAddress((void**)&oa,   g_offs_a);
    cudaGetSymbolAddress((void**)&bx,   g_bsums_x);
    cudaGetSymbolAddress((void**)&ba,   g_bsums_a);
    cudaGetSymbolAddress((void**)&cx,   g_cx);
    cudaGetSymbolAddress((void**)&ca,   g_ca);

    // Side stream + events: created once on first (uncaptured) call, reused.
    static cudaStream_t s2 = nullptr;
    static cudaEvent_t  evFork = nullptr, evJoin = nullptr, evW = nullptr;
    if (s2 == nullptr) {
        cudaStreamCreateWithFlags(&s2, cudaStreamNonBlocking);
        cudaEventCreateWithFlags(&evFork, cudaEventDisableTiming);
        cudaEventCreateWithFlags(&evJoin, cudaEventDisableTiming);
        cudaEventCreateWithFlags(&evW,    cudaEventDisableTiming);
    }

    const int n4        = NNZ_X / 4;                       // 800000
    const int n4_blocks = (n4 + 255) / 256;

    // ---- fork (counters self-restored by scanC; no zero pass) ----
    cudaEventRecord(evFork, 0);
    cudaStreamWaitEvent(s2, evFork, 0);

    // ---- chain B (W convert + adj build) on side stream ----
    wcvt_kernel<<<(IN_DIM * OUT_DIM / 2 + 255) / 256, 256, 0, s2>>>(W, Wh);
    cudaEventRecord(evW, s2);                       // spmm1 depends on Wh
    hist_kernel<<<n4_blocks, 256, 0, s2>>>((const int4*)adj_rows, cnta, n4);
    scanA_kernel<<<N_SCANBLK, SCAN_B, 0, s2>>>(cnta, oa, ba);
    scanC_kernel<<<N_SCANBLK, SCAN_B, 0, s2>>>(oa, ba, cura, cnta, NNZ_ADJ);
    scatter_kernel<1><<<n4_blocks, 256, 0, s2>>>((const int4*)adj_rows, (const int4*)adj_cols,
                                                 (const float4*)adj_vals, cura, ca, n4);
    cudaEventRecord(evJoin, s2);

    // ---- chain A (x build + spmm1) on main stream ----
    hist_kernel<<<n4_blocks, 256>>>((const int4*)x_rows, cntx, n4);
    scanA_kernel<<<N_SCANBLK, SCAN_B>>>(cntx, ox, bx);
    scanC_kernel<<<N_SCANBLK, SCAN_B>>>(ox, bx, curx, cntx, NNZ_X);
    scatter_kernel<0><<<n4_blocks, 256>>>((const int4*)x_rows, (const int4*)x_cols,
                                          (const float4*)x_vals, curx, cx, n4);

    cudaStreamWaitEvent(0, evW, 0);                 // ensure Wh ready
    const int spmm_blocks = (N_NODES * 32 + 255) / 256;   // warp per row
    spmm1_kernel<<<spmm_blocks, 256>>>(ox, cx, Wh, xw);

    // ---- join, then SpMM2 + ReLU ----
    cudaStreamWaitEvent(0, evJoin, 0);
    spmm2_kernel<<<spmm_blocks, 256>>>(oa, ca, xw, out);
}

// round 17
// speedup vs baseline: 1.0188x; 1.0093x over previous
#include <cuda_runtime.h>
#include <cuda_fp16.h>

#define N_NODES 100000
#define IN_DIM  1024
#define OUT_DIM 256
#define NNZ_X   3200000
#define NNZ_ADJ 3200000

#define SCAN_B    1024
#define N_SCANBLK ((N_NODES + SCAN_B - 1) / SCAN_B)   // 98

// ---------------- scratch (__device__ globals; no allocs allowed) ----------
__device__ __half g_xw[(size_t)N_NODES * OUT_DIM];     // 51.2 MB (L2-resident)
__device__ __half g_wh[IN_DIM * OUT_DIM];              // 512 KB

// counts: zero at module load; scanC re-zeroes each replay (self-restoring).
// cur:    rewritten by scanC from offs each replay before scatter uses it.
__device__ int   g_counts_x[N_NODES];
__device__ int   g_counts_a[N_NODES];
__device__ int   g_cur_x[N_NODES];
__device__ int   g_cur_a[N_NODES];
__device__ int   g_offs_x[N_NODES + 1];
__device__ int   g_offs_a[N_NODES + 1];
__device__ int   g_bsums_x[N_SCANBLK];
__device__ int   g_bsums_a[N_SCANBLK];
__device__ int   g_cx[NNZ_X];                          // packed (col<<16)|fp16
__device__ int   g_ca[NNZ_ADJ];                        // packed (col<<15)|q15

// PDL device helpers (sm_90+)
__device__ __forceinline__ void pdl_wait()    { cudaGridDependencySynchronize(); }
__device__ __forceinline__ void pdl_trigger() { cudaTriggerProgrammaticLaunchCompletion(); }

// ---------------- mixed-precision FMA: fp16 x fp16 -> fp32 accum ------------
__device__ __forceinline__ void fma_h2(float& s0, float& s1, int wpair, unsigned short vh) {
    unsigned short h0, h1;
    asm("mov.b32 {%0, %1}, %2;" : "=h"(h0), "=h"(h1) : "r"(wpair));
    asm("fma.rn.f32.f16 %0, %1, %2, %0;" : "+f"(s0) : "h"(h0), "h"(vh));
    asm("fma.rn.f32.f16 %0, %1, %2, %0;" : "+f"(s1) : "h"(h1), "h"(vh));
}

// ---------------- W fp32 -> fp16 -------------------------------------------
__global__ void wcvt_kernel(const float* __restrict__ W, __half* __restrict__ Wh) {
    int i = blockIdx.x * blockDim.x + threadIdx.x;      // over float2 pairs
    if (i < IN_DIM * OUT_DIM / 2) {
        float2 w = __ldcs(reinterpret_cast<const float2*>(W) + i);
        reinterpret_cast<__half2*>(Wh)[i] = __floats2half2_rn(w.x, w.y);
    }
    pdl_trigger();
}

// ---------------- histogram: int4-vectorized, 4 nnz per thread --------------
__global__ void hist_kernel(const int4* __restrict__ rows4, int* __restrict__ counts, int n4) {
    int i = blockIdx.x * blockDim.x + threadIdx.x;
    if (i < n4) {
        int4 r = __ldcs(&rows4[i]);
        atomicAdd(&counts[r.x], 1);
        atomicAdd(&counts[r.y], 1);
        atomicAdd(&counts[r.z], 1);
        atomicAdd(&counts[r.w], 1);
    }
    pdl_trigger();
}

// ---------------- scan A: two-level warp-shuffle exclusive scan --------------
__global__ void scanA_kernel(const int* __restrict__ counts,
                             int* __restrict__ offs, int* __restrict__ bsums) {
    __shared__ int wsum[32];
    int t = threadIdx.x, lane = t & 31, wid = t >> 5;
    int i = blockIdx.x * SCAN_B + t;
    pdl_wait();                                        // counts must be final
    int v = (i < N_NODES) ? counts[i] : 0;
    int s = v;
#pragma unroll
    for (int d = 1; d < 32; d <<= 1) {
        int u = __shfl_up_sync(0xffffffffu, s, d);
        if (lane >= d) s += u;
    }
    if (lane == 31) wsum[wid] = s;
    __syncthreads();
    if (wid == 0) {
        int ws = wsum[lane];
#pragma unroll
        for (int d = 1; d < 32; d <<= 1) {
            int u = __shfl_up_sync(0xffffffffu, ws, d);
            if (lane >= d) ws += u;
        }
        wsum[lane] = ws;
    }
    __syncthreads();
    int incl = s + (wid ? wsum[wid - 1] : 0);
    if (i < N_NODES) offs[i] = incl - v;                // exclusive (local)
    if (t == SCAN_B - 1) bsums[blockIdx.x] = incl;      // inclusive block total
    pdl_trigger();
}

// ---------------- scan C: add prefix; init cursor; reset counts -------------
__global__ void scanC_kernel(int* __restrict__ offs, const int* __restrict__ bsums,
                             int* __restrict__ cur, int* __restrict__ counts, int total) {
    __shared__ int part[4];
    __shared__ int pref;
    int t = threadIdx.x, lane = t & 31, wid = t >> 5;
    pdl_wait();                                        // offs/bsums must be final
    if (t < 128) {
        int v = (t < blockIdx.x) ? bsums[t] : 0;        // blockIdx.x <= 97 < 128
#pragma unroll
        for (int d = 16; d > 0; d >>= 1) v += __shfl_down_sync(0xffffffffu, v, d);
        if (lane == 0) part[wid] = v;
    }
    __syncthreads();
    if (t == 0) pref = part[0] + part[1] + part[2] + part[3];
    __syncthreads();
    int i = blockIdx.x * SCAN_B + t;
    if (i < N_NODES) {
        int o = offs[i] + pref;
        offs[i]   = o;
        cur[i]    = o;                                  // scatter cursor
        counts[i] = 0;                                  // restore for next replay
    }
    if (i == 0) offs[N_NODES] = total;
    pdl_trigger();
}

// ---------------- scatter COO -> CSR: ONE atomic + ONE store per nnz ---------
// MODE 0 (x):   col < 1024   -> p = (col<<16) | fp16(val) bits
// MODE 1 (adj): col < 2^17, val in [0,1) -> p = (col<<15) | round(val*32768) clamped
template <int MODE>
__global__ void scatter_kernel(const int4* __restrict__ rows4, const int4* __restrict__ cols4,
                               const float4* __restrict__ vals4,
                               int* __restrict__ cur, int* __restrict__ cdata, int n4) {
    int i = blockIdx.x * blockDim.x + threadIdx.x;
    pdl_wait();                                        // cur must be initialized
    if (i < n4) {
        int4   r = __ldcs(&rows4[i]);
        int4   c = __ldcs(&cols4[i]);
        float4 v = __ldcs(&vals4[i]);
#define SCAT_ONE(RR, CC, VV)                                                     \
        {                                                                        \
            int p = atomicAdd(&cur[(RR)], 1);                                    \
            int packed;                                                          \
            if (MODE == 0) {                                                     \
                packed = ((CC) << 16) | (int)__half_as_ushort(__float2half_rn(VV)); \
            } else {                                                             \
                int q = __float2int_rn((VV) * 32768.f);                          \
                q = min(q, 32767);                                               \
                packed = ((CC) << 15) | q;                                       \
            }                                                                    \
            cdata[p] = packed;                                                   \
        }
        SCAT_ONE(r.x, c.x, v.x)
        SCAT_ONE(r.y, c.y, v.y)
        SCAT_ONE(r.z, c.z, v.z)
        SCAT_ONE(r.w, c.w, v.w)
#undef SCAT_ONE
    }
    pdl_trigger();
}

// ---------------- SpMM1 step: uniform scalar payload load (no shfl) ---------
#define SPMM1_STEP(IDX)                                                          \
    {                                                                            \
        int p = __ldg(&cdata[(IDX)]);   /* all lanes same addr -> broadcast */   \
        int cc = ((unsigned)p) >> 16;                                            \
        unsigned short vh = (unsigned short)(p & 0xffff);                        \
        int4 wv = __ldg(reinterpret_cast<const int4*>(Wh + (size_t)cc * OUT_DIM) + lane); \
        fma_h2(a0, a1, wv.x, vh);                                                \
        fma_h2(a2, a3, wv.y, vh);                                                \
        fma_h2(a4, a5, wv.z, vh);                                                \
        fma_h2(a6, a7, wv.w, vh);                                                \
    }

// ---------------- SpMM1: warp per row (frozen compute) -----------------------
__global__ void __launch_bounds__(256, 8)
spmm1_kernel(const int* __restrict__ offs, const int* __restrict__ cdata,
             const __half* __restrict__ Wh, __half* __restrict__ xw) {
    int warp = (blockIdx.x * blockDim.x + threadIdx.x) >> 5;
    int lane = threadIdx.x & 31;
    pdl_wait();                                        // offs/cdata must be final
    if (warp >= N_NODES) return;

    int beg = offs[warp];
    int end = offs[warp + 1];

    float a0 = 0.f, a1 = 0.f, a2 = 0.f, a3 = 0.f;
    float a4 = 0.f, a5 = 0.f, a6 = 0.f, a7 = 0.f;

    int base = beg;
    for (; base + 32 <= end; base += 32) {
#pragma unroll
        for (int t = 0; t < 32; t++) SPMM1_STEP(base + t)
    }
    for (; base < end; base++) SPMM1_STEP(base)

    int4 o;
    __half2 h0 = __floats2half2_rn(a0, a1);
    __half2 h1 = __floats2half2_rn(a2, a3);
    __half2 h2 = __floats2half2_rn(a4, a5);
    __half2 h3 = __floats2half2_rn(a6, a7);
    o.x = *reinterpret_cast<int*>(&h0);
    o.y = *reinterpret_cast<int*>(&h1);
    o.z = *reinterpret_cast<int*>(&h2);
    o.w = *reinterpret_cast<int*>(&h3);
    reinterpret_cast<int4*>(xw + (size_t)warp * OUT_DIM)[lane] = o;
    pdl_trigger();
}

// ---------------- SpMM2 step: uniform scalar payload load (no shfl) ---------
#define SPMM2_STEP(IDX)                                                          \
    {                                                                            \
        int p = __ldg(&cdata[(IDX)]);                                            \
        int cc = ((unsigned)p) >> 15;                                            \
        float vv = (float)(p & 0x7fff) * QINV;                                   \
        int4 wv = __ldg(reinterpret_cast<const int4*>(xw + (size_t)cc * OUT_DIM) + lane); \
        float2 f0 = __half22float2(*reinterpret_cast<__half2*>(&wv.x));          \
        float2 f1 = __half22float2(*reinterpret_cast<__half2*>(&wv.y));          \
        float2 f2 = __half22float2(*reinterpret_cast<__half2*>(&wv.z));          \
        float2 f3 = __half22float2(*reinterpret_cast<__half2*>(&wv.w));          \
        a0 = fmaf(vv, f0.x, a0); a1 = fmaf(vv, f0.y, a1);                        \
        a2 = fmaf(vv, f1.x, a2); a3 = fmaf(vv, f1.y, a3);                        \
        a4 = fmaf(vv, f2.x, a4); a5 = fmaf(vv, f2.y, a5);                        \
        a6 = fmaf(vv, f3.x, a6); a7 = fmaf(vv, f3.y, a7);                        \
    }

// ---------------- SpMM2 + ReLU (frozen compute) -------------------------------
__global__ void __launch_bounds__(256, 8)
spmm2_kernel(const int* __restrict__ offs, const int* __restrict__ cdata,
             const __half* __restrict__ xw, float* __restrict__ out) {
    int warp = (blockIdx.x * blockDim.x + threadIdx.x) >> 5;
    int lane = threadIdx.x & 31;
    pdl_wait();                                        // xw must be final
    if (warp >= N_NODES) return;

    int beg = offs[warp];
    int end = offs[warp + 1];

    float a0 = 0.f, a1 = 0.f, a2 = 0.f, a3 = 0.f;
    float a4 = 0.f, a5 = 0.f, a6 = 0.f, a7 = 0.f;

    const float QINV = 1.f / 32768.f;

    int base = beg;
    for (; base + 32 <= end; base += 32) {
#pragma unroll
        for (int t = 0; t < 32; t++) SPMM2_STEP(base + t)
    }
    for (; base < end; base++) SPMM2_STEP(base)

    float4* d = reinterpret_cast<float4*>(out + (size_t)warp * OUT_DIM) + lane * 2;
    __stcs(d,     make_float4(fmaxf(a0, 0.f), fmaxf(a1, 0.f), fmaxf(a2, 0.f), fmaxf(a3, 0.f)));
    __stcs(d + 1, make_float4(fmaxf(a4, 0.f), fmaxf(a5, 0.f), fmaxf(a6, 0.f), fmaxf(a7, 0.f)));
}

// ---------------- PDL launch helper ------------------------------------------
template <typename K, typename... Args>
static inline void launch_pdl(K kernel, dim3 grid, dim3 block, cudaStream_t st, Args... args) {
    cudaLaunchConfig_t cfg = {};
    cfg.gridDim = grid;
    cfg.blockDim = block;
    cfg.stream = st;
    cudaLaunchAttribute attr[1];
    attr[0].id = cudaLaunchAttributeProgrammaticStreamSerialization;
    attr[0].val.programmaticStreamSerializationAllowed = 1;
    cfg.attrs = attr;
    cfg.numAttrs = 1;
    cudaLaunchKernelEx(&cfg, kernel, args...);
}

// ---------------------------------------------------------------------------
extern "C" void kernel_launch(void* const* d_in, const int* in_sizes, int n_in,
                              void* d_out, int out_size) {
    const int*   x_rows   = (const int*)  d_in[0];
    const int*   x_cols   = (const int*)  d_in[1];
    const float* x_vals   = (const float*)d_in[2];
    const int*   adj_rows = (const int*)  d_in[3];
    const int*   adj_cols = (const int*)  d_in[4];
    const float* adj_vals = (const float*)d_in[5];
    const float* W        = (const float*)d_in[6];
    float*       out      = (float*)d_out;

    __half *xw, *Wh;
    int *cntx, *cnta, *curx, *cura, *ox, *oa, *bx, *ba, *cx, *ca;
    cudaGetSymbolAddress((void**)&xw,   g_xw);
    cudaGetSymbolAddress((void**)&Wh,   g_wh);
    cudaGetSymbolAddress((void**)&cntx, g_counts_x);
    cudaGetSymbolAddress((void**)&cnta, g_counts_a);
    cudaGetSymbolAddress((void**)&curx, g_cur_x);
    cudaGetSymbolAddress((void**)&cura, g_cur_a);
    cudaGetSymbolAddress((void**)&ox,   g_offs_x);
    cudaGetSymbolAddress((void**)&oa,   g_offs_a);
    cudaGetSymbolAddress((void**)&bx,   g_bsums_x);
    cudaGetSymbolAddress((void**)&ba,   g_bsums_a);
    cudaGetSymbolAddress((void**)&cx,   g_cx);
    cudaGetSymbolAddress((void**)&ca,   g_ca);

    // Side stream + events: created once on first (uncaptured) call, reused.
    static cudaStream_t s2 = nullptr;
    static cudaEvent_t  evFork = nullptr, evJoin = nullptr, evW = nullptr;
    if (s2 == nullptr) {
        cudaStreamCreateWithFlags(&s2, cudaStreamNonBlocking);
        cudaEventCreateWithFlags(&evFork, cudaEventDisableTiming);
        cudaEventCreateWithFlags(&evJoin, cudaEventDisableTiming);
        cudaEventCreateWithFlags(&evW,    cudaEventDisableTiming);
    }

    const int n4        = NNZ_X / 4;                       // 800000
    const int n4_blocks = (n4 + 255) / 256;

    // ---- fork (counters self-restored by scanC; no zero pass) ----
    cudaEventRecord(evFork, 0);
    cudaStreamWaitEvent(s2, evFork, 0);

    // ---- chain B (W convert + adj build) on side stream, PDL-chained ----
    wcvt_kernel<<<(IN_DIM * OUT_DIM / 2 + 255) / 256, 256, 0, s2>>>(W, Wh);
    cudaEventRecord(evW, s2);                       // spmm1 depends on Wh
    hist_kernel<<<n4_blocks, 256, 0, s2>>>((const int4*)adj_rows, cnta, n4);
    launch_pdl(scanA_kernel, N_SCANBLK, SCAN_B, s2, (const int*)cnta, oa, ba);
    launch_pdl(scanC_kernel, N_SCANBLK, SCAN_B, s2, oa, (const int*)ba, cura, cnta, NNZ_ADJ);
    launch_pdl(scatter_kernel<1>, n4_blocks, 256, s2,
               (const int4*)adj_rows, (const int4*)adj_cols,
               (const float4*)adj_vals, cura, ca, n4);
    cudaEventRecord(evJoin, s2);

    // ---- chain A (x build + spmm1) on main stream, PDL-chained ----
    hist_kernel<<<n4_blocks, 256>>>((const int4*)x_rows, cntx, n4);
    launch_pdl(scanA_kernel, N_SCANBLK, SCAN_B, (cudaStream_t)0, (const int*)cntx, ox, bx);
    launch_pdl(scanC_kernel, N_SCANBLK, SCAN_B, (cudaStream_t)0, ox, (const int*)bx, curx, cntx, NNZ_X);
    launch_pdl(scatter_kernel<0>, n4_blocks, 256, (cudaStream_t)0,
               (const int4*)x_rows, (const int4*)x_cols,
               (const float4*)x_vals, curx, cx, n4);

    cudaStreamWaitEvent(0, evW, 0);                 // ensure Wh ready
    const int spmm_blocks = (N_NODES * 32 + 255) / 256;   // warp per row
    launch_pdl(spmm1_kernel, spmm_blocks, 256, (cudaStream_t)0,
               (const int*)ox, (const int*)cx, (const __half*)Wh, xw);

    // ---- join, then SpMM2 + ReLU ----
    cudaStreamWaitEvent(0, evJoin, 0);
    launch_pdl(spmm2_kernel, spmm_blocks, 256, (cudaStream_t)0,
               (const int*)oa, (const int*)ca, (const __half*)xw, out);
}